// round 3
// baseline (speedup 1.0000x reference)
#include <cuda_runtime.h>

#define BB    2
#define NN    65536
#define KK    16
#define CIN   64
#define CADD  3
#define CTOT  67
#define CMID  16
#define COUT  128
#define INF   1072        // CTOT * CMID
#define MT    16          // points per block
#define NTHR  256

// dynamic smem layout (floats):
//   feat_s : MT*KK*68      = 17408   [m][k][c], c padded 67->68
//   wn_s   : MT*KK*CMID    = 4096    flat, same layout as global
//   pconv_s: MT*INF        = 17152   [m][i]
#define FEAT_F   (MT*KK*68)
#define WN_F     (MT*KK*CMID)
#define PCONV_F  (MT*INF)
#define SMEM_BYTES ((FEAT_F + WN_F + PCONV_F) * 4)

typedef unsigned long long ull;

__device__ __forceinline__ void fma2(ull &d, ull a, ull b) {
    // packed 2x fp32 fma: d.lo += a.lo*b.lo ; d.hi += a.hi*b.hi
    asm("fma.rn.f32x2 %0, %1, %2, %0;" : "+l"(d) : "l"(a), "l"(b));
}

__device__ __forceinline__ float lo32(ull v) {
    return __int_as_float((int)(v & 0xFFFFFFFFull));
}
__device__ __forceinline__ float hi32(ull v) {
    return __int_as_float((int)(v >> 32));
}

__global__ __launch_bounds__(NTHR, 1)
void pconv_linear_kernel(const float* __restrict__ input_feat,
                         const int* __restrict__ nbr,        // int32 (JAX x64 disabled)
                         const float* __restrict__ wn,
                         const float* __restrict__ addf,
                         const float* __restrict__ W,
                         const float* __restrict__ bias,
                         float* __restrict__ out)
{
    extern __shared__ float sm[];
    float* feat_s  = sm;                  // [MT][KK][68]
    float* wn_s    = sm + FEAT_F;         // [MT*KK*CMID]
    float* pconv_s = wn_s + WN_F;         // [MT][INF]

    const int t   = threadIdx.x;
    const int bid = blockIdx.x;
    const int b   = bid / (NN / MT);
    const int m0  = (bid % (NN / MT)) * MT;

    // ---------- load weightnet tile: MT*KK*CMID = 4096 contiguous floats ----------
    {
        const float4* src = (const float4*)(wn + ((size_t)(b * NN + m0)) * KK * CMID);
        float4* dst = (float4*)wn_s;
        #pragma unroll
        for (int r = 0; r < 4; r++) dst[t + r * NTHR] = src[t + r * NTHR];
    }

    // ---------- gather: one thread per (m,k) row ----------
    {
        const int m = t >> 4;
        const int k = t & 15;
        int idx = nbr[((size_t)(b * NN + m0 + m)) * KK + k];
        // fault-proof clamp: wrong dtype shows up as rel_err, not a crash
        idx = min(max(idx, 0), NN - 1);
        const float4* src = (const float4*)(input_feat + ((size_t)b * NN + (size_t)idx) * CIN);
        float* frow = feat_s + (m * KK + k) * 68;
        #pragma unroll
        for (int w = 0; w < 16; w++) {
            float4 v = src[w];
            frow[4 * w + 0] = v.x;
            frow[4 * w + 1] = v.y;
            frow[4 * w + 2] = v.z;
            frow[4 * w + 3] = v.w;
        }
        const float* asrc = addf + (((size_t)(b * NN + m0 + m)) * KK + k) * CADD;
        frow[64] = asrc[0];
        frow[65] = asrc[1];
        frow[66] = asrc[2];
    }
    __syncthreads();

    // ---------- phase 1: pconv[m][c*16+j] = sum_k feat[m][k][c] * wn[m][k][j] ----------
    {
        const int m = t >> 4;
        const int j = t & 15;
        float wreg[KK];
        #pragma unroll
        for (int k = 0; k < KK; k++) wreg[k] = wn_s[(m * KK + k) * CMID + j];

        const float* fb = feat_s + m * KK * 68;
        float* pb = pconv_s + m * INF + j;

        #pragma unroll
        for (int cq = 0; cq < 16; cq++) {      // c = 4*cq .. 4*cq+3
            float a0 = 0.f, a1 = 0.f, a2 = 0.f, a3 = 0.f;
            #pragma unroll
            for (int k = 0; k < KK; k++) {
                float4 f = *(const float4*)(fb + k * 68 + 4 * cq);
                a0 += f.x * wreg[k];
                a1 += f.y * wreg[k];
                a2 += f.z * wreg[k];
                a3 += f.w * wreg[k];
            }
            pb[(4 * cq + 0) * CMID] = a0;
            pb[(4 * cq + 1) * CMID] = a1;
            pb[(4 * cq + 2) * CMID] = a2;
            pb[(4 * cq + 3) * CMID] = a3;
        }
        #pragma unroll
        for (int c = 64; c < 67; c++) {        // additional-feature tail
            float a = 0.f;
            #pragma unroll
            for (int k = 0; k < KK; k++) a += fb[k * 68 + c] * wreg[k];
            pb[c * CMID] = a;
        }
    }
    __syncthreads();

    // ---------- phase 2: out[m][o] = sum_i pconv[m][i] * W[o][i] + bias[o] ----------
    // thread -> o in {o2, o2+64}, m in {mseg*4 .. mseg*4+3}; i packed 2-wide (f32x2)
    {
        const int o2   = t & 63;
        const int mseg = t >> 6;     // constant within a warp -> pconv LDS broadcast

        const float* w0p = W + (size_t)o2 * INF;
        const float* w1p = W + (size_t)(o2 + 64) * INF;
        const float* pA  = pconv_s + (mseg * 4) * INF;

        ull accA[4] = {0ull, 0ull, 0ull, 0ull};   // o2
        ull accB[4] = {0ull, 0ull, 0ull, 0ull};   // o2+64

        for (int i = 0; i < INF; i += 4) {
            double2 w0 = *(const double2*)(w0p + i);   // LDG.128: two packed f32 pairs
            double2 w1 = *(const double2*)(w1p + i);
            const ull w0a = __double_as_longlong(w0.x);
            const ull w0b = __double_as_longlong(w0.y);
            const ull w1a = __double_as_longlong(w1.x);
            const ull w1b = __double_as_longlong(w1.y);
            #pragma unroll
            for (int mm = 0; mm < 4; mm++) {
                double2 p = *(const double2*)(pA + mm * INF + i);  // LDS.128 broadcast
                const ull pa = __double_as_longlong(p.x);
                const ull pb = __double_as_longlong(p.y);
                fma2(accA[mm], w0a, pa);
                fma2(accA[mm], w0b, pb);
                fma2(accB[mm], w1a, pa);
                fma2(accB[mm], w1b, pb);
            }
        }

        const float b0 = bias[o2];
        const float b1 = bias[o2 + 64];
        #pragma unroll
        for (int mm = 0; mm < 4; mm++) {
            const size_t row = ((size_t)(b * NN + m0 + mseg * 4 + mm)) * COUT;
            out[row + o2]      = lo32(accA[mm]) + hi32(accA[mm]) + b0;
            out[row + o2 + 64] = lo32(accB[mm]) + hi32(accB[mm]) + b1;
        }
    }
}

extern "C" void kernel_launch(void* const* d_in, const int* in_sizes, int n_in,
                              void* d_out, int out_size)
{
    // Inputs have pairwise-distinct element counts — dispatch by size so we are
    // correct regardless of metadata ordering (dict order vs sorted pytree order).
    const float* input_feat = 0;   // B*N*C_IN              = 8388608
    const int*   nbr        = 0;   // B*N*K        (int32)  = 2097152
    const float* wn         = 0;   // B*N*K*C_MID           = 33554432
    const float* addf       = 0;   // B*N*K*C_ADD           = 6291456
    const float* W          = 0;   // C_OUT*INF             = 137216
    const float* bias       = 0;   // C_OUT                 = 128

    for (int i = 0; i < n_in; i++) {
        switch (in_sizes[i]) {
            case BB * NN * CIN:        input_feat = (const float*)d_in[i]; break;
            case BB * NN * KK:         nbr        = (const int*)d_in[i];   break;
            case BB * NN * KK * CMID:  wn         = (const float*)d_in[i]; break;
            case BB * NN * KK * CADD:  addf       = (const float*)d_in[i]; break;
            case COUT * INF:           W          = (const float*)d_in[i]; break;
            case COUT:                 bias       = (const float*)d_in[i]; break;
            default: break;
        }
    }
    float* out = (float*)d_out;

    cudaFuncSetAttribute(pconv_linear_kernel,
                         cudaFuncAttributeMaxDynamicSharedMemorySize, SMEM_BYTES);

    const int grid = (BB * NN) / MT;   // 8192 blocks
    pconv_linear_kernel<<<grid, NTHR, SMEM_BYTES>>>(
        input_feat, nbr, wn, addf, W, bias, out);
}

// round 4
// speedup vs baseline: 3.2507x; 3.2507x over previous
#include <cuda_runtime.h>

#define BB    2
#define NN    65536
#define KK    16
#define CIN   64
#define CADD  3
#define CMID  16
#define COUT  128
#define INF   1072
#define INFP  1088          // padded: 8 chunks x 136
#define ICHUNK 136
#define PCTP  20            // pconv_t row pitch (floats)
#define MT    16
#define NTHR  256

#define FEAT_F (MT*KK*68)       // 17408 floats (69632 B)
#define WN_F   (MT*KK*CMID)     //  4096 floats
#define PCT_F  (INFP*PCTP)      // 21760 floats
#define SMEM_BYTES ((FEAT_F + WN_F + PCT_F) * 4)   // 173056 B

typedef unsigned long long ull;

__device__ float g_Wt[INFP * COUT];   // transposed+padded W: [1088][128]

__device__ __forceinline__ void fma2(ull &d, ull a, ull b) {
    asm("fma.rn.f32x2 %0, %1, %2, %0;" : "+l"(d) : "l"(a), "l"(b));
}
__device__ __forceinline__ ull dup2(float x) {
    ull r; asm("mov.b64 %0, {%1, %1};" : "=l"(r) : "f"(x)); return r;
}
__device__ __forceinline__ float lo32(ull v) { return __int_as_float((int)(v & 0xFFFFFFFFull)); }
__device__ __forceinline__ float hi32(ull v) { return __int_as_float((int)(v >> 32)); }

// ---------------- W transpose prelude: W[o][i] -> W_t[i][o], zero-pad i>=1072 ----
__global__ void wt_kernel(const float* __restrict__ W) {
    int id = blockIdx.x * 256 + threadIdx.x;      // 1088*128 = 139264
    if (id < INFP * COUT) {
        int i = id >> 7, o = id & 127;
        g_Wt[id] = (i < INF) ? W[o * INF + i] : 0.0f;
    }
}

// ---------------- fused kernel ----------------
__global__ __launch_bounds__(NTHR, 1)
void pconv_linear_kernel(const float* __restrict__ input_feat,
                         const int* __restrict__ nbr,
                         const float* __restrict__ wn,
                         const float* __restrict__ addf,
                         const float* __restrict__ bias,
                         float* __restrict__ out)
{
    extern __shared__ float sm[];
    float* feat_s = sm;                 // [256 rows][68]
    float* wn_s   = sm + FEAT_F;
    float* pct    = wn_s + WN_F;        // pconv_t [1088][20] (i-major, m inner)
    ull*   part_u = (ull*)sm;           // aliased over feat_s after phase 1 (64KB)

    const int t    = threadIdx.x;
    const int warp = t >> 5;
    const int lane = t & 31;
    const int bid  = blockIdx.x;
    const int b    = bid / (NN / MT);
    const int m0   = (bid % (NN / MT)) * MT;

    // ---- weightnet tile: 4096 contiguous floats ----
    {
        const float4* src = (const float4*)(wn + ((size_t)(b * NN + m0)) * KK * CMID);
        float4* dst = (float4*)wn_s;
        #pragma unroll
        for (int r = 0; r < 4; r++) dst[t + r * NTHR] = src[t + r * NTHR];
    }

    // ---- zero pconv_t padding rows (i = 1072..1087) ----
    if (t < (INFP - INF) * PCTP) pct[INF * PCTP + t] = 0.0f;

    // ---- coalesced gather: warp loads 32 rows, lanes split columns ----
    {
        const int row = warp * 32 + lane;                 // (m,k) flat
        int idx = nbr[(size_t)(b * NN + m0) * KK + row];
        idx = min(max(idx, 0), NN - 1);
        #pragma unroll 4
        for (int j = 0; j < 32; j++) {
            const int ij = __shfl_sync(0xffffffffu, idx, j);
            const int r  = warp * 32 + j;
            float2 v = ((const float2*)(input_feat + ((size_t)b * NN + (size_t)ij) * CIN))[lane];
            *(float2*)(feat_s + r * 68 + 2 * lane) = v;
        }
        const float* asrc = addf + ((size_t)(b * NN + m0) * KK + t) * CADD;
        float* frow = feat_s + t * 68;
        frow[64] = asrc[0]; frow[65] = asrc[1]; frow[66] = asrc[2];
    }
    __syncthreads();

    // ---- phase 1: pconv_t[c*16+j][m] = sum_k feat[m][k][c] * wn[m][k][j] ----
    {
        const int m = t >> 4;
        const int j = t & 15;
        float wreg[KK];
        #pragma unroll
        for (int k = 0; k < KK; k++) wreg[k] = wn_s[(m * KK + k) * CMID + j];

        const float* fb = feat_s + m * KK * 68;

        #pragma unroll
        for (int cq = 0; cq < 16; cq++) {
            float a0 = 0.f, a1 = 0.f, a2 = 0.f, a3 = 0.f;
            #pragma unroll
            for (int k = 0; k < KK; k++) {
                float4 f = *(const float4*)(fb + k * 68 + 4 * cq);
                a0 += f.x * wreg[k];
                a1 += f.y * wreg[k];
                a2 += f.z * wreg[k];
                a3 += f.w * wreg[k];
            }
            pct[((4 * cq + 0) * 16 + j) * PCTP + m] = a0;
            pct[((4 * cq + 1) * 16 + j) * PCTP + m] = a1;
            pct[((4 * cq + 2) * 16 + j) * PCTP + m] = a2;
            pct[((4 * cq + 3) * 16 + j) * PCTP + m] = a3;
        }
        #pragma unroll
        for (int c = 64; c < 67; c++) {
            float a = 0.f;
            #pragma unroll
            for (int k = 0; k < KK; k++) a += fb[k * 68 + c] * wreg[k];
            pct[(c * 16 + j) * PCTP + m] = a;
        }
    }
    __syncthreads();

    // ---- phase 2: warp = i-chunk of 136; lane = o-quad (4 consecutive o);
    //      acc[mp][o] packs m-pairs in f32x2; W read exactly once per block ----
    {
        ull acc[8][4];
        #pragma unroll
        for (int mp = 0; mp < 8; mp++)
            #pragma unroll
            for (int o = 0; o < 4; o++) acc[mp][o] = 0ull;

        const int i0base = warp * ICHUNK;
        const float* wt = g_Wt + 4 * lane;

        for (int blk = 0; blk < ICHUNK / 4; blk++) {
            const int i0 = i0base + blk * 4;
            float4 wv[4];
            #pragma unroll
            for (int di = 0; di < 4; di++)
                wv[di] = *(const float4*)(wt + (size_t)(i0 + di) * COUT);

            #pragma unroll
            for (int di = 0; di < 4; di++) {
                const ull wd0 = dup2(wv[di].x);
                const ull wd1 = dup2(wv[di].y);
                const ull wd2 = dup2(wv[di].z);
                const ull wd3 = dup2(wv[di].w);
                const double2* pr = (const double2*)(pct + (size_t)(i0 + di) * PCTP);
                #pragma unroll
                for (int mq = 0; mq < 4; mq++) {
                    const double2 pv = pr[mq];              // 4 m's at this i (broadcast LDS.128)
                    const ull pa = __double_as_longlong(pv.x);  // (m=4mq,   m=4mq+1)
                    const ull pb = __double_as_longlong(pv.y);  // (m=4mq+2, m=4mq+3)
                    fma2(acc[2*mq  ][0], pa, wd0); fma2(acc[2*mq  ][1], pa, wd1);
                    fma2(acc[2*mq  ][2], pa, wd2); fma2(acc[2*mq  ][3], pa, wd3);
                    fma2(acc[2*mq+1][0], pb, wd0); fma2(acc[2*mq+1][1], pb, wd1);
                    fma2(acc[2*mq+1][2], pb, wd2); fma2(acc[2*mq+1][3], pb, wd3);
                }
            }
        }

        // store per-warp partials (feat_s region is dead now; all threads passed the
        // post-phase-1 barrier, so writing the alias is safe)
        #pragma unroll
        for (int mp = 0; mp < 8; mp++) {
            ulonglong2 v01; v01.x = acc[mp][0]; v01.y = acc[mp][1];
            ulonglong2 v23; v23.x = acc[mp][2]; v23.y = acc[mp][3];
            ull* dst = &part_u[(size_t)((warp * 8 + mp) * COUT + 4 * lane)];
            *(ulonglong2*)(dst)     = v01;
            *(ulonglong2*)(dst + 2) = v23;
        }
    }
    __syncthreads();

    // ---- reduce 8 warp-partials, add bias, write out ----
    {
        const int mp = t >> 5;           // 0..7 -> m pair (2mp, 2mp+1)
        const int o0 = (t & 31) * 4;
        float2 s0 = {0.f,0.f}, s1 = {0.f,0.f}, s2 = {0.f,0.f}, s3 = {0.f,0.f};
        #pragma unroll
        for (int w = 0; w < 8; w++) {
            const ull* q = &part_u[(size_t)((w * 8 + mp) * COUT + o0)];
            ulonglong2 a  = *(const ulonglong2*)q;
            ulonglong2 b2 = *(const ulonglong2*)(q + 2);
            s0.x += lo32(a.x);  s0.y += hi32(a.x);
            s1.x += lo32(a.y);  s1.y += hi32(a.y);
            s2.x += lo32(b2.x); s2.y += hi32(b2.x);
            s3.x += lo32(b2.y); s3.y += hi32(b2.y);
        }
        const float4 bs = *(const float4*)(bias + o0);
        float4 ve; ve.x = s0.x + bs.x; ve.y = s1.x + bs.y; ve.z = s2.x + bs.z; ve.w = s3.x + bs.w;
        float4 vo; vo.x = s0.y + bs.x; vo.y = s1.y + bs.y; vo.z = s2.y + bs.z; vo.w = s3.y + bs.w;
        const size_t re = ((size_t)(b * NN + m0 + 2 * mp)) * COUT + o0;
        const size_t ro = ((size_t)(b * NN + m0 + 2 * mp + 1)) * COUT + o0;
        *(float4*)(out + re) = ve;
        *(float4*)(out + ro) = vo;
    }
}

extern "C" void kernel_launch(void* const* d_in, const int* in_sizes, int n_in,
                              void* d_out, int out_size)
{
    const float* input_feat = 0;   // 8388608
    const int*   nbr        = 0;   // 2097152 (int32)
    const float* wn         = 0;   // 33554432
    const float* addf       = 0;   // 6291456
    const float* W          = 0;   // 137216
    const float* bias       = 0;   // 128

    for (int i = 0; i < n_in; i++) {
        switch (in_sizes[i]) {
            case BB * NN * CIN:        input_feat = (const float*)d_in[i]; break;
            case BB * NN * KK:         nbr        = (const int*)d_in[i];   break;
            case BB * NN * KK * CMID:  wn         = (const float*)d_in[i]; break;
            case BB * NN * KK * CADD:  addf       = (const float*)d_in[i]; break;
            case COUT * INF:           W          = (const float*)d_in[i]; break;
            case COUT:                 bias       = (const float*)d_in[i]; break;
            default: break;
        }
    }
    float* out = (float*)d_out;

    cudaFuncSetAttribute(pconv_linear_kernel,
                         cudaFuncAttributeMaxDynamicSharedMemorySize, SMEM_BYTES);

    wt_kernel<<<(INFP * COUT + 255) / 256, 256>>>(W);

    const int grid = (BB * NN) / MT;   // 8192 blocks
    pconv_linear_kernel<<<grid, NTHR, SMEM_BYTES>>>(
        input_feat, nbr, wn, addf, bias, out);
}

// round 8
// speedup vs baseline: 4.6842x; 1.4410x over previous
#include <cuda_runtime.h>
#include <cuda_bf16.h>
#include <cstdint>

#define BB    2
#define NN    65536
#define KK    16
#define CIN   64
#define CADD  3
#define CMID  16
#define COUT  128
#define INF   1072
#define INFP  1088
#define MT    16
#define PTS   (BB*NN)

typedef unsigned long long ull;
typedef unsigned int u32;

// -------- device scratch (zero-init at load; pad cols [1072,1088) never written) ----
__device__ __align__(16) u32 g_Asc[(size_t)PTS * INFP];   // pconv: bf16 hi(lo16)|lo(hi16)
__device__ __align__(16) u32 g_Wb [(size_t)COUT * INFP];  // W, same packing, zero-padded

// ---------------- helpers ----------------
__device__ __forceinline__ void fma2(ull &d, ull a, ull b){
    asm("fma.rn.f32x2 %0, %1, %2, %0;" : "+l"(d) : "l"(a), "l"(b));
}
__device__ __forceinline__ ull dup2f(float x){ ull r; asm("mov.b64 %0, {%1,%1};" : "=l"(r) : "f"(x)); return r; }
__device__ __forceinline__ float lo32(ull v){ return __int_as_float((int)(u32)v); }
__device__ __forceinline__ float hi32(ull v){ return __int_as_float((int)(v>>32)); }

__device__ __forceinline__ u32 pack_hilo(float a){
    __nv_bfloat16 h = __float2bfloat16(a);
    float hf = __bfloat162float(h);
    __nv_bfloat16 l = __float2bfloat16(a - hf);
    return ((u32)__bfloat16_as_ushort(l) << 16) | (u32)__bfloat16_as_ushort(h);
}
__device__ __forceinline__ u32 s2u(const void* p){
    u32 a; asm("{ .reg .u64 t; cvta.to.shared.u64 t, %1; cvt.u32.u64 %0, t; }" : "=r"(a) : "l"(p)); return a;
}

#define LDSM4(rr, addr) \
    asm volatile("ldmatrix.sync.aligned.m8n8.x4.shared.b16 {%0,%1,%2,%3}, [%4];" \
        : "=r"((rr)[0]), "=r"((rr)[1]), "=r"((rr)[2]), "=r"((rr)[3]) : "r"(addr))

#define MMA16816(d, a, b0, b1) \
    asm volatile("mma.sync.aligned.m16n8k16.row.col.f32.bf16.bf16.f32 " \
        "{%0,%1,%2,%3},{%4,%5,%6,%7},{%8,%9},{%0,%1,%2,%3};" \
        : "+f"((d)[0]), "+f"((d)[1]), "+f"((d)[2]), "+f"((d)[3]) \
        : "r"((a)[0]), "r"((a)[1]), "r"((a)[2]), "r"((a)[3]), "r"(b0), "r"(b1))

// ---------------- prelude: W -> bf16 hi/lo packed, padded ----------------
__global__ void wb_kernel(const float* __restrict__ W){
    int id = blockIdx.x * 256 + threadIdx.x;
    if (id < COUT * INFP) {
        int o = id / INFP, i = id % INFP;
        g_Wb[id] = (i < INF) ? pack_hilo(W[o * INF + i]) : 0u;
    }
}

// ---------------- kernel A: gather + pconv -> scratch ----------------
__global__ __launch_bounds__(256, 2)
void pconv_kernel(const float* __restrict__ input_feat,
                  const int* __restrict__ nbr,
                  const float* __restrict__ wn,
                  const float* __restrict__ addf)
{
    extern __shared__ float feat_s[];    // [256 rows][68]
    const int t = threadIdx.x, warp = t >> 5, lane = t & 31;
    const int bid = blockIdx.x;
    const int b  = bid / (NN / MT);
    const int m0 = (bid % (NN / MT)) * MT;

    {   // coalesced gather (round-4 verified pattern)
        const int row = warp * 32 + lane;
        int idx = nbr[(size_t)(b * NN + m0) * KK + row];
        idx = min(max(idx, 0), NN - 1);
        #pragma unroll 4
        for (int j = 0; j < 32; j++) {
            const int ij = __shfl_sync(0xffffffffu, idx, j);
            const int r  = warp * 32 + j;
            float2 v = ((const float2*)(input_feat + ((size_t)b * NN + (size_t)ij) * CIN))[lane];
            *(float2*)(feat_s + r * 68 + 2 * lane) = v;
        }
        const float* asrc = addf + ((size_t)(b * NN + m0) * KK + t) * CADD;
        float* frow = feat_s + t * 68;
        frow[64] = asrc[0]; frow[65] = asrc[1]; frow[66] = asrc[2];
    }
    __syncthreads();

    const int m = t >> 4, j = t & 15;
    const size_t pt = (size_t)(b * NN + m0 + m);

    ull wd[KK];
    #pragma unroll
    for (int k = 0; k < KK; k++) wd[k] = dup2f(wn[(pt * KK + k) * CMID + j]);

    const float* fb = feat_s + m * KK * 68;
    u32* dst = g_Asc + pt * INFP + j;

    for (int cp = 0; cp < 33; cp++) {           // c = 2cp, 2cp+1
        ull a0 = 0, a1 = 0;
        #pragma unroll
        for (int k = 0; k < 8; k++) {
            fma2(a0, *(const ull*)(fb + k * 68 + 2 * cp), wd[k]);
            fma2(a1, *(const ull*)(fb + (k + 8) * 68 + 2 * cp), wd[k + 8]);
        }
        dst[(2 * cp)     * CMID] = pack_hilo(lo32(a0) + lo32(a1));
        dst[(2 * cp + 1) * CMID] = pack_hilo(hi32(a0) + hi32(a1));
    }
    {   // c = 66 tail
        float a = 0.f;
        #pragma unroll
        for (int k = 0; k < KK; k++) a += fb[k * 68 + 66] * lo32(wd[k]);
        dst[66 * CMID] = pack_hilo(a);
    }
}

// ---------------- kernel B: mma.sync bf16 GEMM [128m x 128o x 1088k] ----------------
#define PITCHB   144            // bf16 row pitch in bytes (9*16 -> LDSM-legal, conflict-free)
#define A_HI_OFF 0
#define A_LO_OFF 18432
#define B_HI_OFF 36864
#define B_LO_OFF 55296
#define STG      73728
#define SMEM_GEMM (2*STG)       // 147456 B

__device__ __forceinline__ void load_chunk(char* smem, int sbase,
                                           const u32* __restrict__ A,
                                           const u32* __restrict__ B, int t)
{
    #pragma unroll
    for (int it = 0; it < 8; it++) {
        const int id = t + it * 256;        // 0..2047
        const int r = id >> 4, q = id & 15; // row, 16B-quad within 64-k chunk
        const size_t go = (size_t)r * INFP + q * 4;
        const int so = r * PITCHB + q * 8;
        uint4 u = *(const uint4*)(A + go);
        *(uint2*)(smem + sbase + A_HI_OFF + so) =
            make_uint2(__byte_perm(u.x, u.y, 0x5410), __byte_perm(u.z, u.w, 0x5410));
        *(uint2*)(smem + sbase + A_LO_OFF + so) =
            make_uint2(__byte_perm(u.x, u.y, 0x7632), __byte_perm(u.z, u.w, 0x7632));
        uint4 v = *(const uint4*)(B + go);
        *(uint2*)(smem + sbase + B_HI_OFF + so) =
            make_uint2(__byte_perm(v.x, v.y, 0x5410), __byte_perm(v.z, v.w, 0x5410));
        *(uint2*)(smem + sbase + B_LO_OFF + so) =
            make_uint2(__byte_perm(v.x, v.y, 0x7632), __byte_perm(v.z, v.w, 0x7632));
    }
}

__global__ __launch_bounds__(256, 1)
void gemm_kernel(const float* __restrict__ bias, float* __restrict__ out)
{
    extern __shared__ char smem[];
    const u32 sb = s2u(smem);
    const int t = threadIdx.x, wid = t >> 5, lane = t & 31;
    const size_t tile0 = (size_t)blockIdx.x * 128;
    const int m0w = (wid & 3) * 32;       // warp m-offset (32 rows)
    const int n0w = (wid >> 2) * 64;      // warp n-offset (64 cols)

    const u32* Ag = g_Asc + tile0 * INFP;
    const u32* Bg = g_Wb;

    float D[2][8][4] = {};                // [m-tile16][n-tile8][frag]

    // ldmatrix per-lane address bases (16B-aligned: PITCHB=144)
    const u32 a_base = (u32)((m0w + (lane & 15)) * PITCHB + ((lane >> 4) & 1) * 16);
    const u32 b_base = (u32)((n0w + ((lane >> 4) & 1) * 8 + (lane & 7)) * PITCHB
                             + ((lane >> 3) & 1) * 16);

    load_chunk(smem, 0, Ag, Bg, t);
    __syncthreads();

    for (int kc = 0; kc < 17; kc++) {
        const int st = kc & 1;
        if (kc < 16)
            load_chunk(smem, (1 - st) * STG, Ag + (kc + 1) * 64, Bg + (kc + 1) * 64, t);

        const u32 AH = sb + st * STG + A_HI_OFF;
        const u32 AL = sb + st * STG + A_LO_OFF;
        const u32 BH = sb + st * STG + B_HI_OFF;
        const u32 BL = sb + st * STG + B_LO_OFF;

        #pragma unroll
        for (int ks = 0; ks < 4; ks++) {
            u32 ah[2][4], al[2][4];
            #pragma unroll
            for (int mt = 0; mt < 2; mt++) {
                const u32 off = a_base + mt * 16 * PITCHB + ks * 32;
                LDSM4(ah[mt], AH + off);
                LDSM4(al[mt], AL + off);
            }
            u32 bh[4][4], bl[4][4];
            #pragma unroll
            for (int np = 0; np < 4; np++) {
                const u32 off = b_base + np * 16 * PITCHB + ks * 32;
                LDSM4(bh[np], BH + off);
                LDSM4(bl[np], BL + off);
            }
            #pragma unroll
            for (int mt = 0; mt < 2; mt++)
                #pragma unroll
                for (int np = 0; np < 4; np++) {
                    MMA16816(D[mt][2*np],   ah[mt], bh[np][0], bh[np][1]);
                    MMA16816(D[mt][2*np],   al[mt], bh[np][0], bh[np][1]);
                    MMA16816(D[mt][2*np],   ah[mt], bl[np][0], bl[np][1]);
                    MMA16816(D[mt][2*np+1], ah[mt], bh[np][2], bh[np][3]);
                    MMA16816(D[mt][2*np+1], al[mt], bh[np][2], bh[np][3]);
                    MMA16816(D[mt][2*np+1], ah[mt], bl[np][2], bl[np][3]);
                }
        }
        __syncthreads();
    }

    // epilogue: + bias, write fp32
    const int gid = lane >> 2, tid4 = lane & 3;
    #pragma unroll
    for (int nt = 0; nt < 8; nt++) {
        const int col = n0w + nt * 8 + tid4 * 2;
        const float2 bp = *(const float2*)(bias + col);
        #pragma unroll
        for (int mt = 0; mt < 2; mt++) {
            const float* Dp = D[mt][nt];
            const size_t row = tile0 + m0w + mt * 16 + gid;
            *(float2*)(out + row * COUT + col)       = make_float2(Dp[0] + bp.x, Dp[1] + bp.y);
            *(float2*)(out + (row + 8) * COUT + col) = make_float2(Dp[2] + bp.x, Dp[3] + bp.y);
        }
    }
}

// ---------------- launch ----------------
extern "C" void kernel_launch(void* const* d_in, const int* in_sizes, int n_in,
                              void* d_out, int out_size)
{
    const float* input_feat = 0;   // 8388608
    const int*   nbr        = 0;   // 2097152 (int32)
    const float* wn         = 0;   // 33554432
    const float* addf       = 0;   // 6291456
    const float* W          = 0;   // 137216
    const float* bias       = 0;   // 128

    for (int i = 0; i < n_in; i++) {
        switch (in_sizes[i]) {
            case BB * NN * CIN:        input_feat = (const float*)d_in[i]; break;
            case BB * NN * KK:         nbr        = (const int*)d_in[i];   break;
            case BB * NN * KK * CMID:  wn         = (const float*)d_in[i]; break;
            case BB * NN * KK * CADD:  addf       = (const float*)d_in[i]; break;
            case COUT * INF:           W          = (const float*)d_in[i]; break;
            case COUT:                 bias       = (const float*)d_in[i]; break;
            default: break;
        }
    }
    float* out = (float*)d_out;

    wb_kernel<<<(COUT * INFP + 255) / 256, 256>>>(W);

    cudaFuncSetAttribute(pconv_kernel, cudaFuncAttributeMaxDynamicSharedMemorySize, 256 * 68 * 4);
    pconv_kernel<<<(BB * NN) / MT, 256, 256 * 68 * 4>>>(input_feat, nbr, wn, addf);

    cudaFuncSetAttribute(gemm_kernel, cudaFuncAttributeMaxDynamicSharedMemorySize, SMEM_GEMM);
    gemm_kernel<<<PTS / 128, 256, SMEM_GEMM>>>(bias, out);
}

// round 9
// speedup vs baseline: 4.8935x; 1.0447x over previous
#include <cuda_runtime.h>
#include <cuda_bf16.h>
#include <cstdint>

#define BB    2
#define NN    65536
#define KK    16
#define CIN   64
#define CADD  3
#define CMID  16
#define COUT  128
#define INF   1072
#define INFP  1088
#define MT    16
#define PTS   (BB*NN)

typedef unsigned long long ull;
typedef unsigned int u32;
typedef unsigned short u16;

// -------- device scratch: bf16 hi/lo planes (zero-init covers k-pads) --------
__device__ __align__(16) u16 g_Ahi[(size_t)PTS * INFP];
__device__ __align__(16) u16 g_Alo[(size_t)PTS * INFP];
__device__ __align__(16) u16 g_Bhi[COUT * INFP];
__device__ __align__(16) u16 g_Blo[COUT * INFP];

// ---------------- helpers ----------------
__device__ __forceinline__ void fma2(ull &d, ull a, ull b){
    asm("fma.rn.f32x2 %0, %1, %2, %0;" : "+l"(d) : "l"(a), "l"(b));
}
__device__ __forceinline__ ull add2(ull a, ull b){
    ull r; asm("add.rn.f32x2 %0, %1, %2;" : "=l"(r) : "l"(a), "l"(b)); return r;
}
__device__ __forceinline__ ull dup2f(float x){ ull r; asm("mov.b64 %0, {%1,%1};" : "=l"(r) : "f"(x)); return r; }
__device__ __forceinline__ float lo32(ull v){ return __int_as_float((int)(u32)v); }
__device__ __forceinline__ float hi32(ull v){ return __int_as_float((int)(v>>32)); }

__device__ __forceinline__ void emit_hilo(u16* ph, u16* pl, float v){
    __nv_bfloat16 h = __float2bfloat16(v);
    float fh = __bfloat162float(h);
    __nv_bfloat16 l = __float2bfloat16(v - fh);
    *ph = __bfloat16_as_ushort(h);
    *pl = __bfloat16_as_ushort(l);
}
__device__ __forceinline__ u32 s2u(const void* p){
    u32 a; asm("{ .reg .u64 t; cvta.to.shared.u64 t, %1; cvt.u32.u64 %0, t; }" : "=r"(a) : "l"(p)); return a;
}
__device__ __forceinline__ void cp16(u32 dst, const void* src){
    asm volatile("cp.async.cg.shared.global [%0], [%1], 16;" :: "r"(dst), "l"(src));
}

#define LDSM4(rr, addr) \
    asm volatile("ldmatrix.sync.aligned.m8n8.x4.shared.b16 {%0,%1,%2,%3}, [%4];" \
        : "=r"((rr)[0]), "=r"((rr)[1]), "=r"((rr)[2]), "=r"((rr)[3]) : "r"(addr))

#define MMA16816(d, a, b0, b1) \
    asm volatile("mma.sync.aligned.m16n8k16.row.col.f32.bf16.bf16.f32 " \
        "{%0,%1,%2,%3},{%4,%5,%6,%7},{%8,%9},{%0,%1,%2,%3};" \
        : "+f"((d)[0]), "+f"((d)[1]), "+f"((d)[2]), "+f"((d)[3]) \
        : "r"((a)[0]), "r"((a)[1]), "r"((a)[2]), "r"((a)[3]), "r"(b0), "r"(b1))

// ---------------- prelude: W -> hi/lo planes, zero-padded ----------------
__global__ void wb_kernel(const float* __restrict__ W){
    int id = blockIdx.x * 256 + threadIdx.x;
    if (id < COUT * INFP) {
        int o = id / INFP, i = id % INFP;
        float w = (i < INF) ? W[o * INF + i] : 0.0f;
        emit_hilo(&g_Bhi[id], &g_Blo[id], w);
    }
}

// ---------------- kernel A: gather + pconv -> hi/lo scratch planes ----------------
__global__ __launch_bounds__(256, 2)
void pconv_kernel(const float* __restrict__ input_feat,
                  const int* __restrict__ nbr,
                  const float* __restrict__ wn,
                  const float* __restrict__ addf)
{
    extern __shared__ float feat_s[];    // [256 rows][68]
    const int t = threadIdx.x, warp = t >> 5, lane = t & 31;
    const int bid = blockIdx.x;
    const int b  = bid / (NN / MT);
    const int m0 = (bid % (NN / MT)) * MT;

    {   // coalesced gather
        const int row = warp * 32 + lane;
        int idx = nbr[(size_t)(b * NN + m0) * KK + row];
        idx = min(max(idx, 0), NN - 1);
        #pragma unroll 4
        for (int j = 0; j < 32; j++) {
            const int ij = __shfl_sync(0xffffffffu, idx, j);
            const int r  = warp * 32 + j;
            float2 v = ((const float2*)(input_feat + ((size_t)b * NN + (size_t)ij) * CIN))[lane];
            *(float2*)(feat_s + r * 68 + 2 * lane) = v;
        }
        const float* asrc = addf + ((size_t)(b * NN + m0) * KK + t) * CADD;
        float* frow = feat_s + t * 68;
        frow[64] = asrc[0]; frow[65] = asrc[1]; frow[66] = asrc[2];
    }
    __syncthreads();

    const int m = t >> 4, j = t & 15;
    const size_t pt = (size_t)(b * NN + m0 + m);

    ull wd[KK];
    #pragma unroll
    for (int k = 0; k < KK; k++) wd[k] = dup2f(wn[(pt * KK + k) * CMID + j]);

    const float* fb = feat_s + m * KK * 68;
    u16* dhi = g_Ahi + pt * INFP + j;
    u16* dlo = g_Alo + pt * INFP + j;

    for (int cp = 0; cp < 33; cp++) {           // c = 2cp, 2cp+1
        ull a0 = 0, a1 = 0;
        #pragma unroll
        for (int k = 0; k < 8; k++) {
            fma2(a0, *(const ull*)(fb + k * 68 + 2 * cp), wd[k]);
            fma2(a1, *(const ull*)(fb + (k + 8) * 68 + 2 * cp), wd[k + 8]);
        }
        const ull s = add2(a0, a1);
        emit_hilo(dhi + (2 * cp)     * CMID, dlo + (2 * cp)     * CMID, lo32(s));
        emit_hilo(dhi + (2 * cp + 1) * CMID, dlo + (2 * cp + 1) * CMID, hi32(s));
    }
    {   // c = 66 tail (c=67 stays zero from static init)
        float a = 0.f;
        #pragma unroll
        for (int k = 0; k < KK; k++) a += fb[k * 68 + 66] * lo32(wd[k]);
        emit_hilo(dhi + 66 * CMID, dlo + 66 * CMID, a);
    }
}

// ---------------- kernel B: cp.async-pipelined mma.sync GEMM ----------------
#define CK       32               // k per chunk
#define NCH      (INFP/CK)        // 34
#define PITCH    80               // smem row pitch (bytes): 64B data + 16B pad
#define PLP      (128*PITCH)      // 10240 B per plane
#define STG      (4*PLP)          // 40960 B per stage
#define SMEM_GEMM (2*STG)         // 81920 B

__device__ __forceinline__ void load_chunk(u32 sbase, int kc, size_t tile0, int t)
{
    const u16* g0 = g_Ahi + tile0 * INFP;
    const u16* g1 = g_Alo + tile0 * INFP;
    #pragma unroll
    for (int it = 0; it < 8; it++) {
        const int p   = it >> 1;                    // plane 0..3 (compile-time)
        const int rem = t + (it & 1) * 256;         // 0..511
        const int row = rem >> 2, q = rem & 3;
        const u16* g = (p == 0) ? g0 : (p == 1) ? g1 : (p == 2) ? g_Bhi : g_Blo;
        cp16(sbase + p * PLP + row * PITCH + q * 16,
             g + (size_t)row * INFP + kc * CK + q * 8);
    }
    asm volatile("cp.async.commit_group;" ::: "memory");
}

__global__ __launch_bounds__(256, 2)
void gemm_kernel(const float* __restrict__ bias, float* __restrict__ out)
{
    extern __shared__ char smem[];
    const u32 sb = s2u(smem);
    const int t = threadIdx.x, wid = t >> 5, lane = t & 31;
    const size_t tile0 = (size_t)blockIdx.x * 128;
    const int m0w = (wid & 3) * 32;
    const int n0w = (wid >> 2) * 64;

    float D[2][8][4] = {};

    const u32 a_base = (u32)((m0w + (lane & 15)) * PITCH + ((lane >> 4) & 1) * 16);
    const u32 b_base = (u32)((n0w + ((lane >> 4) & 1) * 8 + (lane & 7)) * PITCH
                             + ((lane >> 3) & 1) * 16);

    load_chunk(sb, 0, tile0, t);
    load_chunk(sb + STG, 1, tile0, t);

    for (int c = 0; c < NCH; c++) {
        const int st = c & 1;
        if (c < NCH - 1) asm volatile("cp.async.wait_group 1;" ::: "memory");
        else             asm volatile("cp.async.wait_group 0;" ::: "memory");
        __syncthreads();

        const u32 AH = sb + st * STG;
        const u32 AL = AH + PLP;
        const u32 BH = AH + 2 * PLP;
        const u32 BL = AH + 3 * PLP;

        #pragma unroll
        for (int ks = 0; ks < 2; ks++) {
            u32 ah[2][4], al[2][4];
            #pragma unroll
            for (int mt = 0; mt < 2; mt++) {
                const u32 off = a_base + mt * 16 * PITCH + ks * 32;
                LDSM4(ah[mt], AH + off);
                LDSM4(al[mt], AL + off);
            }
            #pragma unroll
            for (int np = 0; np < 4; np++) {
                u32 bh[4], bl[4];
                const u32 off = b_base + np * 16 * PITCH + ks * 32;
                LDSM4(bh, BH + off);
                LDSM4(bl, BL + off);
                #pragma unroll
                for (int mt = 0; mt < 2; mt++) {
                    MMA16816(D[mt][2*np],   ah[mt], bh[0], bh[1]);
                    MMA16816(D[mt][2*np],   al[mt], bh[0], bh[1]);
                    MMA16816(D[mt][2*np],   ah[mt], bl[0], bl[1]);
                    MMA16816(D[mt][2*np+1], ah[mt], bh[2], bh[3]);
                    MMA16816(D[mt][2*np+1], al[mt], bh[2], bh[3]);
                    MMA16816(D[mt][2*np+1], ah[mt], bl[2], bl[3]);
                }
            }
        }
        __syncthreads();
        if (c + 2 < NCH) load_chunk(sb + st * STG, c + 2, tile0, t);
    }

    // epilogue: + bias, fp32 out
    const int gid = lane >> 2, tid4 = lane & 3;
    #pragma unroll
    for (int nt = 0; nt < 8; nt++) {
        const int col = n0w + nt * 8 + tid4 * 2;
        const float2 bp = *(const float2*)(bias + col);
        #pragma unroll
        for (int mt = 0; mt < 2; mt++) {
            const float* Dp = D[mt][nt];
            const size_t row = tile0 + m0w + mt * 16 + gid;
            *(float2*)(out + row * COUT + col)       = make_float2(Dp[0] + bp.x, Dp[1] + bp.y);
            *(float2*)(out + (row + 8) * COUT + col) = make_float2(Dp[2] + bp.x, Dp[3] + bp.y);
        }
    }
}

// ---------------- launch ----------------
extern "C" void kernel_launch(void* const* d_in, const int* in_sizes, int n_in,
                              void* d_out, int out_size)
{
    const float* input_feat = 0;   // 8388608
    const int*   nbr        = 0;   // 2097152 (int32)
    const float* wn         = 0;   // 33554432
    const float* addf       = 0;   // 6291456
    const float* W          = 0;   // 137216
    const float* bias       = 0;   // 128

    for (int i = 0; i < n_in; i++) {
        switch (in_sizes[i]) {
            case BB * NN * CIN:        input_feat = (const float*)d_in[i]; break;
            case BB * NN * KK:         nbr        = (const int*)d_in[i];   break;
            case BB * NN * KK * CMID:  wn         = (const float*)d_in[i]; break;
            case BB * NN * KK * CADD:  addf       = (const float*)d_in[i]; break;
            case COUT * INF:           W          = (const float*)d_in[i]; break;
            case COUT:                 bias       = (const float*)d_in[i]; break;
            default: break;
        }
    }
    float* out = (float*)d_out;

    wb_kernel<<<(COUT * INFP + 255) / 256, 256>>>(W);

    cudaFuncSetAttribute(pconv_kernel, cudaFuncAttributeMaxDynamicSharedMemorySize, 256 * 68 * 4);
    pconv_kernel<<<(BB * NN) / MT, 256, 256 * 68 * 4>>>(input_feat, nbr, wn, addf);

    cudaFuncSetAttribute(gemm_kernel, cudaFuncAttributeMaxDynamicSharedMemorySize, SMEM_GEMM);
    gemm_kernel<<<PTS / 128, 256, SMEM_GEMM>>>(bias, out);
}

// round 12
// speedup vs baseline: 5.7555x; 1.1761x over previous
#include <cuda_runtime.h>
#include <cuda_bf16.h>
#include <cstdint>

#define BB    2
#define NN    65536
#define KK    16
#define CIN   64
#define CADD  3
#define CMID  16
#define COUT  128
#define INF   1072
#define INFP  1088
#define MT    8
#define PTS   (BB*NN)

typedef unsigned long long ull;
typedef unsigned int u32;
typedef unsigned short u16;

// -------- device scratch: bf16 hi/lo planes (zero-init covers k-pads) --------
__device__ __align__(16) u16 g_Ahi[(size_t)PTS * INFP];
__device__ __align__(16) u16 g_Alo[(size_t)PTS * INFP];
__device__ __align__(16) u16 g_Bhi[COUT * INFP];
__device__ __align__(16) u16 g_Blo[COUT * INFP];

// ---------------- helpers ----------------
__device__ __forceinline__ void fma2(ull &d, ull a, ull b){
    asm("fma.rn.f32x2 %0, %1, %2, %0;" : "+l"(d) : "l"(a), "l"(b));
}
__device__ __forceinline__ ull sub2(ull a, ull b){
    ull r; asm("sub.rn.f32x2 %0, %1, %2;" : "=l"(r) : "l"(a), "l"(b)); return r;
}
__device__ __forceinline__ ull dup2f(float x){ ull r; asm("mov.b64 %0, {%1,%1};" : "=l"(r) : "f"(x)); return r; }
__device__ __forceinline__ float lo32(ull v){ return __int_as_float((int)(u32)v); }
__device__ __forceinline__ float hi32(ull v){ return __int_as_float((int)(v>>32)); }

// pack 2 f32 (lo from bits[31:0], hi from bits[63:32]) -> bf16x2 u32 [hi16=c1 | lo16=c0]
__device__ __forceinline__ u32 cvt2(ull v){
    u32 d; float a = hi32(v), b = lo32(v);
    asm("cvt.rn.bf16x2.f32 %0, %1, %2;" : "=r"(d) : "f"(a), "f"(b));
    return d;
}
// rebuild packed f32 pair from bf16x2 (lo16 -> lo f32 bits<<16, hi16 -> hi f32 bits)
__device__ __forceinline__ ull bf2f2(u32 p){
    u32 flo = p << 16;
    u32 fhi = p & 0xFFFF0000u;
    ull r; asm("mov.b64 %0, {%1, %2};" : "=l"(r) : "r"(flo), "r"(fhi));
    return r;
}
__device__ __forceinline__ void emit_hilo(u16* ph, u16* pl, float v){
    __nv_bfloat16 h = __float2bfloat16(v);
    float fh = __bfloat162float(h);
    __nv_bfloat16 l = __float2bfloat16(v - fh);
    *ph = __bfloat16_as_ushort(h);
    *pl = __bfloat16_as_ushort(l);
}
__device__ __forceinline__ u32 s2u(const void* p){
    u32 a; asm("{ .reg .u64 t; cvta.to.shared.u64 t, %1; cvt.u32.u64 %0, t; }" : "=r"(a) : "l"(p)); return a;
}
__device__ __forceinline__ void cp16(u32 dst, const void* src){
    asm volatile("cp.async.cg.shared.global [%0], [%1], 16;" :: "r"(dst), "l"(src));
}

#define LDSM4(rr, addr) \
    asm volatile("ldmatrix.sync.aligned.m8n8.x4.shared.b16 {%0,%1,%2,%3}, [%4];" \
        : "=r"((rr)[0]), "=r"((rr)[1]), "=r"((rr)[2]), "=r"((rr)[3]) : "r"(addr))

#define MMA16816(d, a, b0, b1) \
    asm volatile("mma.sync.aligned.m16n8k16.row.col.f32.bf16.bf16.f32 " \
        "{%0,%1,%2,%3},{%4,%5,%6,%7},{%8,%9},{%0,%1,%2,%3};" \
        : "+f"((d)[0]), "+f"((d)[1]), "+f"((d)[2]), "+f"((d)[3]) \
        : "r"((a)[0]), "r"((a)[1]), "r"((a)[2]), "r"((a)[3]), "r"(b0), "r"(b1))

// ---------------- W prelude ----------------
__global__ void wb_kernel(const float* __restrict__ W){
    int id = blockIdx.x * 256 + threadIdx.x;
    if (id < COUT * INFP) {
        int o = id / INFP, i = id % INFP;
        float w = (i < INF) ? W[o * INF + i] : 0.0f;
        emit_hilo(&g_Bhi[id], &g_Blo[id], w);
    }
}

// ---------------- kernel A: gather + pconv -> hi/lo planes ----------------
__global__ __launch_bounds__(128, 4)
void pconv_kernel(const float* __restrict__ input_feat,
                  const int* __restrict__ nbr,
                  const float* __restrict__ wn,
                  const float* __restrict__ addf)
{
    __shared__ float feat_s[MT * KK * 68];   // 34816 B
    const int t = threadIdx.x, warp = t >> 5, lane = t & 31;
    const int bid = blockIdx.x;
    const int b  = bid / (NN / MT);
    const int m0 = (bid % (NN / MT)) * MT;

    {   // coalesced gather: 4 warps x 32 rows
        const int row = warp * 32 + lane;
        int idx = nbr[(size_t)(b * NN + m0) * KK + row];
        idx = min(max(idx, 0), NN - 1);
        #pragma unroll 4
        for (int j = 0; j < 32; j++) {
            const int ij = __shfl_sync(0xffffffffu, idx, j);
            const int r  = warp * 32 + j;
            float2 v = ((const float2*)(input_feat + ((size_t)b * NN + (size_t)ij) * CIN))[lane];
            *(float2*)(feat_s + r * 68 + 2 * lane) = v;
        }
        const float* asrc = addf + ((size_t)(b * NN + m0) * KK + t) * CADD;
        float* frow = feat_s + t * 68;
        frow[64] = asrc[0]; frow[65] = asrc[1]; frow[66] = asrc[2];
        frow[67] = 0.0f;                       // c=67 pad -> exact zeros emitted
    }
    __syncthreads();

    const int m = t >> 4, j = t & 15;
    const size_t pt = (size_t)(b * NN + m0 + m);

    ull wd[KK];
    #pragma unroll
    for (int k = 0; k < KK; k++) wd[k] = dup2f(wn[(pt * KK + k) * CMID + j]);

    const float* fb = feat_s + m * KK * 68;
    u16* dhi = g_Ahi + pt * INFP + j;
    u16* dlo = g_Alo + pt * INFP + j;

    #pragma unroll 4
    for (int cq = 0; cq < 17; cq++) {            // c = 4cq .. 4cq+3 (c=67 is zero)
        ull a01 = 0, a23 = 0;
        #pragma unroll
        for (int k = 0; k < KK; k++) {
            double2 f = *(const double2*)(fb + k * 68 + 4 * cq);   // LDS.128 broadcast
            fma2(a01, __double_as_longlong(f.x), wd[k]);
            fma2(a23, __double_as_longlong(f.y), wd[k]);
        }
        const u32 h01 = cvt2(a01);
        const u32 h23 = cvt2(a23);
        const u32 l01 = cvt2(sub2(a01, bf2f2(h01)));
        const u32 l23 = cvt2(sub2(a23, bf2f2(h23)));
        const int i0 = (4 * cq) * CMID;          // + j via dhi base
        dhi[i0]            = (u16)h01;
        dhi[i0 + CMID]     = (u16)(h01 >> 16);
        dhi[i0 + 2 * CMID] = (u16)h23;
        dhi[i0 + 3 * CMID] = (u16)(h23 >> 16);
        dlo[i0]            = (u16)l01;
        dlo[i0 + CMID]     = (u16)(l01 >> 16);
        dlo[i0 + 2 * CMID] = (u16)l23;
        dlo[i0 + 3 * CMID] = (u16)(l23 >> 16);
    }
}

// ---------------- kernel B: cp.async-pipelined mma.sync GEMM (unchanged) ----------------
#define CK       32
#define NCH      (INFP/CK)        // 34
#define PITCH    80
#define PLP      (128*PITCH)
#define STG      (4*PLP)
#define SMEM_GEMM (2*STG)

__device__ __forceinline__ void load_chunk(u32 sbase, int kc, size_t tile0, int t)
{
    const u16* g0 = g_Ahi + tile0 * INFP;
    const u16* g1 = g_Alo + tile0 * INFP;
    #pragma unroll
    for (int it = 0; it < 8; it++) {
        const int p   = it >> 1;
        const int rem = t + (it & 1) * 256;
        const int row = rem >> 2, q = rem & 3;
        const u16* g = (p == 0) ? g0 : (p == 1) ? g1 : (p == 2) ? g_Bhi : g_Blo;
        cp16(sbase + p * PLP + row * PITCH + q * 16,
             g + (size_t)row * INFP + kc * CK + q * 8);
    }
    asm volatile("cp.async.commit_group;" ::: "memory");
}

__global__ __launch_bounds__(256, 2)
void gemm_kernel(const float* __restrict__ bias, float* __restrict__ out)
{
    extern __shared__ char smem[];
    const u32 sb = s2u(smem);
    const int t = threadIdx.x, wid = t >> 5, lane = t & 31;
    const size_t tile0 = (size_t)blockIdx.x * 128;
    const int m0w = (wid & 3) * 32;
    const int n0w = (wid >> 2) * 64;

    float D[2][8][4] = {};

    const u32 a_base = (u32)((m0w + (lane & 15)) * PITCH + ((lane >> 4) & 1) * 16);
    const u32 b_base = (u32)((n0w + ((lane >> 4) & 1) * 8 + (lane & 7)) * PITCH
                             + ((lane >> 3) & 1) * 16);

    load_chunk(sb, 0, tile0, t);
    load_chunk(sb + STG, 1, tile0, t);

    for (int c = 0; c < NCH; c++) {
        const int st = c & 1;
        if (c < NCH - 1) asm volatile("cp.async.wait_group 1;" ::: "memory");
        else             asm volatile("cp.async.wait_group 0;" ::: "memory");
        __syncthreads();

        const u32 AH = sb + st * STG;
        const u32 AL = AH + PLP;
        const u32 BH = AH + 2 * PLP;
        const u32 BL = AH + 3 * PLP;

        #pragma unroll
        for (int ks = 0; ks < 2; ks++) {
            u32 ah[2][4], al[2][4];
            #pragma unroll
            for (int mt = 0; mt < 2; mt++) {
                const u32 off = a_base + mt * 16 * PITCH + ks * 32;
                LDSM4(ah[mt], AH + off);
                LDSM4(al[mt], AL + off);
            }
            #pragma unroll
            for (int np = 0; np < 4; np++) {
                u32 bh[4], bl[4];
                const u32 off = b_base + np * 16 * PITCH + ks * 32;
                LDSM4(bh, BH + off);
                LDSM4(bl, BL + off);
                #pragma unroll
                for (int mt = 0; mt < 2; mt++) {
                    MMA16816(D[mt][2*np],   ah[mt], bh[0], bh[1]);
                    MMA16816(D[mt][2*np],   al[mt], bh[0], bh[1]);
                    MMA16816(D[mt][2*np],   ah[mt], bl[0], bl[1]);
                    MMA16816(D[mt][2*np+1], ah[mt], bh[2], bh[3]);
                    MMA16816(D[mt][2*np+1], al[mt], bh[2], bh[3]);
                    MMA16816(D[mt][2*np+1], ah[mt], bl[2], bl[3]);
                }
            }
        }
        __syncthreads();
        if (c + 2 < NCH) load_chunk(sb + st * STG, c + 2, tile0, t);
    }

    const int gid = lane >> 2, tid4 = lane & 3;
    #pragma unroll
    for (int nt = 0; nt < 8; nt++) {
        const int col = n0w + nt * 8 + tid4 * 2;
        const float2 bp = *(const float2*)(bias + col);
        #pragma unroll
        for (int mt = 0; mt < 2; mt++) {
            const float* Dp = D[mt][nt];
            const size_t row = tile0 + m0w + mt * 16 + gid;
            *(float2*)(out + row * COUT + col)       = make_float2(Dp[0] + bp.x, Dp[1] + bp.y);
            *(float2*)(out + (row + 8) * COUT + col) = make_float2(Dp[2] + bp.x, Dp[3] + bp.y);
        }
    }
}

// ---------------- launch ----------------
extern "C" void kernel_launch(void* const* d_in, const int* in_sizes, int n_in,
                              void* d_out, int out_size)
{
    const float* input_feat = 0;   // 8388608
    const int*   nbr        = 0;   // 2097152 (int32)
    const float* wn         = 0;   // 33554432
    const float* addf       = 0;   // 6291456
    const float* W          = 0;   // 137216
    const float* bias       = 0;   // 128

    for (int i = 0; i < n_in; i++) {
        switch (in_sizes[i]) {
            case BB * NN * CIN:        input_feat = (const float*)d_in[i]; break;
            case BB * NN * KK:         nbr        = (const int*)d_in[i];   break;
            case BB * NN * KK * CMID:  wn         = (const float*)d_in[i]; break;
            case BB * NN * KK * CADD:  addf       = (const float*)d_in[i]; break;
            case COUT * INF:           W          = (const float*)d_in[i]; break;
            case COUT:                 bias       = (const float*)d_in[i]; break;
            default: break;
        }
    }
    float* out = (float*)d_out;

    // pconv first (independent of wb) so the fixed ncu sample index lands on a
    // heavy kernel instead of wb_kernel.
    pconv_kernel<<<(BB * NN) / MT, 128>>>(input_feat, nbr, wn, addf);

    wb_kernel<<<(COUT * INFP + 255) / 256, 256>>>(W);

    cudaFuncSetAttribute(gemm_kernel, cudaFuncAttributeMaxDynamicSharedMemorySize, SMEM_GEMM);
    gemm_kernel<<<PTS / 128, 256, SMEM_GEMM>>>(bias, out);
}

// round 14
// speedup vs baseline: 7.8517x; 1.3642x over previous
#include <cuda_runtime.h>
#include <cuda_fp16.h>
#include <cstdint>

#define BB    2
#define NN    65536
#define KK    16
#define CIN   64
#define CADD  3
#define CMID  16
#define COUT  128
#define INF   1072
#define INFP  1088
#define MT    8
#define PTS   (BB*NN)

typedef unsigned long long ull;
typedef unsigned int u32;
typedef unsigned short u16;

// -------- device scratch: fp16 planes (zero-init covers k-pads) --------
__device__ __align__(16) u16 g_A [(size_t)PTS * INFP];   // pconv, fp16
__device__ __align__(16) u16 g_Bh[COUT * INFP];          // W hi (fp16)
__device__ __align__(16) u16 g_Bl[COUT * INFP];          // W lo (fp16 residual)

// ---------------- helpers ----------------
__device__ __forceinline__ void fma2(ull &d, ull a, ull b){
    asm("fma.rn.f32x2 %0, %1, %2, %0;" : "+l"(d) : "l"(a), "l"(b));
}
__device__ __forceinline__ ull dup2f(float x){ ull r; asm("mov.b64 %0, {%1,%1};" : "=l"(r) : "f"(x)); return r; }
__device__ __forceinline__ float lo32(ull v){ return __int_as_float((int)(u32)v); }
__device__ __forceinline__ float hi32(ull v){ return __int_as_float((int)(v>>32)); }

// pack 2 f32 (lo->lo16, hi->hi16) into f16x2
__device__ __forceinline__ u32 cvtf16x2(ull v){
    u32 d; float a = hi32(v), b = lo32(v);
    asm("cvt.rn.f16x2.f32 %0, %1, %2;" : "=r"(d) : "f"(a), "f"(b));
    return d;
}
__device__ __forceinline__ u32 s2u(const void* p){
    u32 a; asm("{ .reg .u64 t; cvta.to.shared.u64 t, %1; cvt.u32.u64 %0, t; }" : "=r"(a) : "l"(p)); return a;
}
__device__ __forceinline__ void cp16(u32 dst, const void* src){
    asm volatile("cp.async.cg.shared.global [%0], [%1], 16;" :: "r"(dst), "l"(src));
}
__device__ __forceinline__ void cp8(u32 dst, const void* src){
    asm volatile("cp.async.ca.shared.global [%0], [%1], 8;" :: "r"(dst), "l"(src));
}

#define LDSM4(rr, addr) \
    asm volatile("ldmatrix.sync.aligned.m8n8.x4.shared.b16 {%0,%1,%2,%3}, [%4];" \
        : "=r"((rr)[0]), "=r"((rr)[1]), "=r"((rr)[2]), "=r"((rr)[3]) : "r"(addr))

#define MMAF16(d, a, b0, b1) \
    asm volatile("mma.sync.aligned.m16n8k16.row.col.f32.f16.f16.f32 " \
        "{%0,%1,%2,%3},{%4,%5,%6,%7},{%8,%9},{%0,%1,%2,%3};" \
        : "+f"((d)[0]), "+f"((d)[1]), "+f"((d)[2]), "+f"((d)[3]) \
        : "r"((a)[0]), "r"((a)[1]), "r"((a)[2]), "r"((a)[3]), "r"(b0), "r"(b1))

// ---------------- W prelude: fp16 hi + residual lo ----------------
__global__ void wb_kernel(const float* __restrict__ W){
    int id = blockIdx.x * 256 + threadIdx.x;
    if (id < COUT * INFP) {
        int o = id / INFP, i = id % INFP;
        float w = (i < INF) ? W[o * INF + i] : 0.0f;
        __half h = __float2half_rn(w);
        __half l = __float2half_rn(w - __half2float(h));
        g_Bh[id] = __half_as_ushort(h);
        g_Bl[id] = __half_as_ushort(l);
    }
}

// ---------------- kernel A: gather (cp.async) + pconv -> fp16 plane ----------------
__global__ __launch_bounds__(128, 4)
void pconv_kernel(const float* __restrict__ input_feat,
                  const int* __restrict__ nbr,
                  const float* __restrict__ wn,
                  const float* __restrict__ addf)
{
    __shared__ float feat_s[MT * KK * 68];   // 34816 B
    const int t = threadIdx.x, warp = t >> 5, lane = t & 31;
    const int bid = blockIdx.x;
    const int b  = bid / (NN / MT);
    const int m0 = (bid % (NN / MT)) * MT;
    const u32 fs = s2u(feat_s);

    {   // coalesced async gather: 4 warps x 32 rows, 8B per lane
        const int row = warp * 32 + lane;
        int idx = nbr[(size_t)(b * NN + m0) * KK + row];
        idx = min(max(idx, 0), NN - 1);
        #pragma unroll 8
        for (int j = 0; j < 32; j++) {
            const int ij = __shfl_sync(0xffffffffu, idx, j);
            const int r  = warp * 32 + j;
            cp8(fs + (r * 68 + 2 * lane) * 4,
                input_feat + ((size_t)b * NN + (size_t)ij) * CIN + 2 * lane);
        }
        asm volatile("cp.async.commit_group;" ::: "memory");
        const float* asrc = addf + ((size_t)(b * NN + m0) * KK + t) * CADD;
        float a0 = asrc[0], a1 = asrc[1], a2 = asrc[2];
        asm volatile("cp.async.wait_group 0;" ::: "memory");
        float* frow = feat_s + t * 68;
        frow[64] = a0; frow[65] = a1; frow[66] = a2;
        frow[67] = 0.0f;                       // c=67 pad -> exact zeros
    }
    __syncthreads();

    const int m = t >> 4, j = t & 15;
    const size_t pt = (size_t)(b * NN + m0 + m);

    ull wd[KK];
    #pragma unroll
    for (int k = 0; k < KK; k++) wd[k] = dup2f(wn[(pt * KK + k) * CMID + j]);

    const float* fb = feat_s + m * KK * 68;
    u16* dst = g_A + pt * INFP + j;

    #pragma unroll 4
    for (int cq = 0; cq < 17; cq++) {            // c = 4cq .. 4cq+3
        ull a01 = 0, a23 = 0;
        #pragma unroll
        for (int k = 0; k < KK; k++) {
            double2 f = *(const double2*)(fb + k * 68 + 4 * cq);   // LDS.128 broadcast
            fma2(a01, __double_as_longlong(f.x), wd[k]);
            fma2(a23, __double_as_longlong(f.y), wd[k]);
        }
        const u32 h01 = cvtf16x2(a01);
        const u32 h23 = cvtf16x2(a23);
        const int i0 = (4 * cq) * CMID;
        dst[i0]            = (u16)h01;
        dst[i0 + CMID]     = (u16)(h01 >> 16);
        dst[i0 + 2 * CMID] = (u16)h23;
        dst[i0 + 3 * CMID] = (u16)(h23 >> 16);
    }
}

// ---------------- kernel B: 2-term fp16 mma.sync GEMM ----------------
#define CK       32
#define NCH      (INFP/CK)        // 34
#define PITCH    80               // smem row pitch (64B data + 16B pad)
#define PLP      (128*PITCH)      // 10240 B per plane
#define STG      (3*PLP)          // 30720 B per stage (A, Bh, Bl)
#define SMEM_GEMM (2*STG)         // 61440 B

__device__ __forceinline__ void load_chunk(u32 sbase, int kc, size_t tile0, int t)
{
    const u16* gA = g_A + tile0 * INFP;
    #pragma unroll
    for (int it = 0; it < 6; it++) {
        const int p   = it >> 1;                 // plane: 0=A, 1=Bh, 2=Bl
        const int rem = t + (it & 1) * 256;      // 0..511
        const int row = rem >> 2, q = rem & 3;
        const u16* g = (p == 0) ? gA : (p == 1) ? g_Bh : g_Bl;
        cp16(sbase + p * PLP + row * PITCH + q * 16,
             g + (size_t)row * INFP + kc * CK + q * 8);
    }
    asm volatile("cp.async.commit_group;" ::: "memory");
}

__global__ __launch_bounds__(256, 2)
void gemm_kernel(const float* __restrict__ bias, float* __restrict__ out)
{
    extern __shared__ char smem[];
    const u32 sb = s2u(smem);
    const int t = threadIdx.x, wid = t >> 5, lane = t & 31;
    const size_t tile0 = (size_t)blockIdx.x * 128;
    const int m0w = (wid & 3) * 32;
    const int n0w = (wid >> 2) * 64;

    float D[2][8][4] = {};

    const u32 a_base = (u32)((m0w + (lane & 15)) * PITCH + ((lane >> 4) & 1) * 16);
    const u32 b_base = (u32)((n0w + ((lane >> 4) & 1) * 8 + (lane & 7)) * PITCH
                             + ((lane >> 3) & 1) * 16);

    load_chunk(sb, 0, tile0, t);
    load_chunk(sb + STG, 1, tile0, t);

    for (int c = 0; c < NCH; c++) {
        const int st = c & 1;
        if (c < NCH - 1) asm volatile("cp.async.wait_group 1;" ::: "memory");
        else             asm volatile("cp.async.wait_group 0;" ::: "memory");
        __syncthreads();

        const u32 AA = sb + st * STG;
        const u32 BH = AA + PLP;
        const u32 BL = AA + 2 * PLP;

        #pragma unroll
        for (int ks = 0; ks < 2; ks++) {
            u32 aa[2][4];
            #pragma unroll
            for (int mt = 0; mt < 2; mt++)
                LDSM4(aa[mt], AA + a_base + mt * 16 * PITCH + ks * 32);
            #pragma unroll
            for (int np = 0; np < 4; np++) {
                u32 bh[4], bl[4];
                const u32 off = b_base + np * 16 * PITCH + ks * 32;
                LDSM4(bh, BH + off);
                LDSM4(bl, BL + off);
                #pragma unroll
                for (int mt = 0; mt < 2; mt++) {
                    MMAF16(D[mt][2*np],   aa[mt], bh[0], bh[1]);
                    MMAF16(D[mt][2*np],   aa[mt], bl[0], bl[1]);
                    MMAF16(D[mt][2*np+1], aa[mt], bh[2], bh[3]);
                    MMAF16(D[mt][2*np+1], aa[mt], bl[2], bl[3]);
                }
            }
        }
        __syncthreads();
        if (c + 2 < NCH) load_chunk(sb + st * STG, c + 2, tile0, t);
    }

    const int gid = lane >> 2, tid4 = lane & 3;
    #pragma unroll
    for (int nt = 0; nt < 8; nt++) {
        const int col = n0w + nt * 8 + tid4 * 2;
        const float2 bp = *(const float2*)(bias + col);
        #pragma unroll
        for (int mt = 0; mt < 2; mt++) {
            const float* Dp = D[mt][nt];
            const size_t row = tile0 + m0w + mt * 16 + gid;
            *(float2*)(out + row * COUT + col)       = make_float2(Dp[0] + bp.x, Dp[1] + bp.y);
            *(float2*)(out + (row + 8) * COUT + col) = make_float2(Dp[2] + bp.x, Dp[3] + bp.y);
        }
    }
}

// ---------------- launch ----------------
extern "C" void kernel_launch(void* const* d_in, const int* in_sizes, int n_in,
                              void* d_out, int out_size)
{
    const float* input_feat = 0;   // 8388608
    const int*   nbr        = 0;   // 2097152 (int32)
    const float* wn         = 0;   // 33554432
    const float* addf       = 0;   // 6291456
    const float* W          = 0;   // 137216
    const float* bias       = 0;   // 128

    for (int i = 0; i < n_in; i++) {
        switch (in_sizes[i]) {
            case BB * NN * CIN:        input_feat = (const float*)d_in[i]; break;
            case BB * NN * KK:         nbr        = (const int*)d_in[i];   break;
            case BB * NN * KK * CMID:  wn         = (const float*)d_in[i]; break;
            case BB * NN * KK * CADD:  addf       = (const float*)d_in[i]; break;
            case COUT * INF:           W          = (const float*)d_in[i]; break;
            case COUT:                 bias       = (const float*)d_in[i]; break;
            default: break;
        }
    }
    float* out = (float*)d_out;

    pconv_kernel<<<(BB * NN) / MT, 128>>>(input_feat, nbr, wn, addf);

    wb_kernel<<<(COUT * INFP + 255) / 256, 256>>>(W);

    cudaFuncSetAttribute(gemm_kernel, cudaFuncAttributeMaxDynamicSharedMemorySize, SMEM_GEMM);
    gemm_kernel<<<PTS / 128, 256, SMEM_GEMM>>>(bias, out);
}

// round 15
// speedup vs baseline: 10.3363x; 1.3164x over previous
#include <cuda_runtime.h>
#include <cuda_fp16.h>
#include <cstdint>

#define BB    2
#define NN    65536
#define KK    16
#define CIN   64
#define CADD  3
#define CMID  16
#define COUT  128
#define INF   1072
#define INFP  1088
#define MT    8
#define PTS   (BB*NN)
#define PITCHM 1092            // floats per m-block in feat_s (KK*68 + 4 pad -> bank shift)

typedef unsigned long long ull;
typedef unsigned int u32;
typedef unsigned short u16;

// -------- device scratch: fp16 planes (zero-init covers k-pads) --------
__device__ __align__(16) u16 g_A [(size_t)PTS * INFP];   // pconv, fp16
__device__ __align__(16) u16 g_Bh[COUT * INFP];          // W, fp16

// ---------------- helpers ----------------
__device__ __forceinline__ void fma2(ull &d, ull a, ull b){
    asm("fma.rn.f32x2 %0, %1, %2, %0;" : "+l"(d) : "l"(a), "l"(b));
}
__device__ __forceinline__ ull dup2f(float x){ ull r; asm("mov.b64 %0, {%1,%1};" : "=l"(r) : "f"(x)); return r; }
__device__ __forceinline__ float lo32(ull v){ return __int_as_float((int)(u32)v); }
__device__ __forceinline__ float hi32(ull v){ return __int_as_float((int)(v>>32)); }

__device__ __forceinline__ u32 cvtf16x2(ull v){
    u32 d; float a = hi32(v), b = lo32(v);
    asm("cvt.rn.f16x2.f32 %0, %1, %2;" : "=r"(d) : "f"(a), "f"(b));
    return d;
}
__device__ __forceinline__ u32 s2u(const void* p){
    u32 a; asm("{ .reg .u64 t; cvta.to.shared.u64 t, %1; cvt.u32.u64 %0, t; }" : "=r"(a) : "l"(p)); return a;
}
__device__ __forceinline__ void cp16(u32 dst, const void* src){
    asm volatile("cp.async.cg.shared.global [%0], [%1], 16;" :: "r"(dst), "l"(src));
}

#define LDSM4(rr, addr) \
    asm volatile("ldmatrix.sync.aligned.m8n8.x4.shared.b16 {%0,%1,%2,%3}, [%4];" \
        : "=r"((rr)[0]), "=r"((rr)[1]), "=r"((rr)[2]), "=r"((rr)[3]) : "r"(addr))

#define MMAF16(d, a, b0, b1) \
    asm volatile("mma.sync.aligned.m16n8k16.row.col.f32.f16.f16.f32 " \
        "{%0,%1,%2,%3},{%4,%5,%6,%7},{%8,%9},{%0,%1,%2,%3};" \
        : "+f"((d)[0]), "+f"((d)[1]), "+f"((d)[2]), "+f"((d)[3]) \
        : "r"((a)[0]), "r"((a)[1]), "r"((a)[2]), "r"((a)[3]), "r"(b0), "r"(b1))

// ---------------- W prelude: fp16 ----------------
__global__ void wb_kernel(const float* __restrict__ W){
    int id = blockIdx.x * 256 + threadIdx.x;
    if (id < COUT * INFP) {
        int o = id / INFP, i = id % INFP;
        float w = (i < INF) ? W[o * INF + i] : 0.0f;
        g_Bh[id] = __half_as_ushort(__float2half_rn(w));
    }
}

// ---------------- kernel A: gather (cp16) + pconv -> fp16 plane ----------------
__global__ __launch_bounds__(128, 4)
void pconv_kernel(const float* __restrict__ input_feat,
                  const int* __restrict__ nbr,
                  const float* __restrict__ wn,
                  const float* __restrict__ addf)
{
    __shared__ float feat_s[MT * PITCHM];    // 34944 B
    const int t = threadIdx.x, warp = t >> 5, lane = t & 31;
    const int bid = blockIdx.x;
    const int b  = bid / (NN / MT);
    const int m0 = (bid % (NN / MT)) * MT;
    const u32 fs = s2u(feat_s);

    {   // async gather: warp covers 32 rows; each cp16 instr loads 2 rows (16 lanes/row)
        const int row = warp * 32 + lane;
        int idx = nbr[(size_t)(b * NN + m0) * KK + row];
        idx = min(max(idx, 0), NN - 1);
        const int half = lane >> 4;          // 0/1: which row this lane serves
        const int l16  = lane & 15;
        #pragma unroll 8
        for (int j = 0; j < 16; j++) {
            const int r  = warp * 32 + 2 * j + half;
            const int ij = __shfl_sync(0xffffffffu, idx, 2 * j + half);
            const int mm = r >> 4, kk = r & 15;
            cp16(fs + (mm * PITCHM + kk * 68 + l16 * 4) * 4,
                 input_feat + ((size_t)b * NN + (size_t)ij) * CIN + l16 * 4);
        }
        asm volatile("cp.async.commit_group;" ::: "memory");
        const float* asrc = addf + ((size_t)(b * NN + m0) * KK + t) * CADD;
        float a0 = asrc[0], a1 = asrc[1], a2 = asrc[2];
        asm volatile("cp.async.wait_group 0;" ::: "memory");
        float* frow = feat_s + (t >> 4) * PITCHM + (t & 15) * 68;
        frow[64] = a0; frow[65] = a1; frow[66] = a2;
        frow[67] = 0.0f;                     // c=67 pad -> exact zeros
    }
    __syncthreads();

    const int m = t >> 4, j = t & 15;
    const size_t pt = (size_t)(b * NN + m0 + m);

    ull wd[KK];
    #pragma unroll
    for (int k = 0; k < KK; k++) wd[k] = dup2f(wn[(pt * KK + k) * CMID + j]);

    const float* fb = feat_s + m * PITCHM;
    u16* dst = g_A + pt * INFP + j;

    #pragma unroll 4
    for (int cq = 0; cq < 17; cq++) {            // c = 4cq .. 4cq+3
        ull a01 = 0, a23 = 0;
        #pragma unroll
        for (int k = 0; k < KK; k++) {
            double2 f = *(const double2*)(fb + k * 68 + 4 * cq);   // conflict-free broadcast
            fma2(a01, __double_as_longlong(f.x), wd[k]);
            fma2(a23, __double_as_longlong(f.y), wd[k]);
        }
        const u32 h01 = cvtf16x2(a01);
        const u32 h23 = cvtf16x2(a23);
        const int i0 = (4 * cq) * CMID;
        dst[i0]            = (u16)h01;
        dst[i0 + CMID]     = (u16)(h01 >> 16);
        dst[i0 + 2 * CMID] = (u16)h23;
        dst[i0 + 3 * CMID] = (u16)(h23 >> 16);
    }
}

// ---------------- kernel B: single-term fp16 mma.sync GEMM ----------------
#define CK       32
#define NCH      (INFP/CK)        // 34
#define PITCH    80               // smem row pitch (64B data + 16B pad)
#define PLP      (128*PITCH)      // 10240 B per plane
#define STG      (2*PLP)          // 20480 B per stage (A, B)
#define SMEM_GEMM (2*STG)         // 40960 B

__device__ __forceinline__ void load_chunk(u32 sbase, int kc, size_t tile0, int t)
{
    const u16* gA = g_A + tile0 * INFP;
    #pragma unroll
    for (int it = 0; it < 4; it++) {
        const int p   = it >> 1;                 // plane: 0=A, 1=B
        const int rem = t + (it & 1) * 256;      // 0..511
        const int row = rem >> 2, q = rem & 3;
        const u16* g = (p == 0) ? gA : g_Bh;
        cp16(sbase + p * PLP + row * PITCH + q * 16,
             g + (size_t)row * INFP + kc * CK + q * 8);
    }
    asm volatile("cp.async.commit_group;" ::: "memory");
}

__global__ __launch_bounds__(256, 2)
void gemm_kernel(const float* __restrict__ bias, float* __restrict__ out)
{
    extern __shared__ char smem[];
    const u32 sb = s2u(smem);
    const int t = threadIdx.x, wid = t >> 5, lane = t & 31;
    const size_t tile0 = (size_t)blockIdx.x * 128;
    const int m0w = (wid & 3) * 32;
    const int n0w = (wid >> 2) * 64;

    float D[2][8][4] = {};

    const u32 a_base = (u32)((m0w + (lane & 15)) * PITCH + ((lane >> 4) & 1) * 16);
    const u32 b_base = (u32)((n0w + ((lane >> 4) & 1) * 8 + (lane & 7)) * PITCH
                             + ((lane >> 3) & 1) * 16);

    load_chunk(sb, 0, tile0, t);
    load_chunk(sb + STG, 1, tile0, t);

    for (int c = 0; c < NCH; c++) {
        const int st = c & 1;
        if (c < NCH - 1) asm volatile("cp.async.wait_group 1;" ::: "memory");
        else             asm volatile("cp.async.wait_group 0;" ::: "memory");
        __syncthreads();

        const u32 AA = sb + st * STG;
        const u32 BH = AA + PLP;

        #pragma unroll
        for (int ks = 0; ks < 2; ks++) {
            u32 aa[2][4];
            #pragma unroll
            for (int mt = 0; mt < 2; mt++)
                LDSM4(aa[mt], AA + a_base + mt * 16 * PITCH + ks * 32);
            #pragma unroll
            for (int np = 0; np < 4; np++) {
                u32 bh[4];
                LDSM4(bh, BH + b_base + np * 16 * PITCH + ks * 32);
                #pragma unroll
                for (int mt = 0; mt < 2; mt++) {
                    MMAF16(D[mt][2*np],   aa[mt], bh[0], bh[1]);
                    MMAF16(D[mt][2*np+1], aa[mt], bh[2], bh[3]);
                }
            }
        }
        __syncthreads();
        if (c + 2 < NCH) load_chunk(sb + st * STG, c + 2, tile0, t);
    }

    const int gid = lane >> 2, tid4 = lane & 3;
    #pragma unroll
    for (int nt = 0; nt < 8; nt++) {
        const int col = n0w + nt * 8 + tid4 * 2;
        const float2 bp = *(const float2*)(bias + col);
        #pragma unroll
        for (int mt = 0; mt < 2; mt++) {
            const float* Dp = D[mt][nt];
            const size_t row = tile0 + m0w + mt * 16 + gid;
            *(float2*)(out + row * COUT + col)       = make_float2(Dp[0] + bp.x, Dp[1] + bp.y);
            *(float2*)(out + (row + 8) * COUT + col) = make_float2(Dp[2] + bp.x, Dp[3] + bp.y);
        }
    }
}

// ---------------- launch ----------------
extern "C" void kernel_launch(void* const* d_in, const int* in_sizes, int n_in,
                              void* d_out, int out_size)
{
    const float* input_feat = 0;   // 8388608
    const int*   nbr        = 0;   // 2097152 (int32)
    const float* wn         = 0;   // 33554432
    const float* addf       = 0;   // 6291456
    const float* W          = 0;   // 137216
    const float* bias       = 0;   // 128

    for (int i = 0; i < n_in; i++) {
        switch (in_sizes[i]) {
            case BB * NN * CIN:        input_feat = (const float*)d_in[i]; break;
            case BB * NN * KK:         nbr        = (const int*)d_in[i];   break;
            case BB * NN * KK * CMID:  wn         = (const float*)d_in[i]; break;
            case BB * NN * KK * CADD:  addf       = (const float*)d_in[i]; break;
            case COUT * INF:           W          = (const float*)d_in[i]; break;
            case COUT:                 bias       = (const float*)d_in[i]; break;
            default: break;
        }
    }
    float* out = (float*)d_out;

    pconv_kernel<<<(BB * NN) / MT, 128>>>(input_feat, nbr, wn, addf);

    wb_kernel<<<(COUT * INFP + 255) / 256, 256>>>(W);

    cudaFuncSetAttribute(gemm_kernel, cudaFuncAttributeMaxDynamicSharedMemorySize, SMEM_GEMM);
    gemm_kernel<<<PTS / 128, 256, SMEM_GEMM>>>(bias, out);
}